// round 14
// baseline (speedup 1.0000x reference)
#include <cuda_runtime.h>

// Problem constants (fixed by the dataset):
//   x_in:    [N,1,H,W]   float32
//   filters: [N,81,H,W]  float32
//   bias:    [N,1,H,W]   float32
//   out:     [N,1,H,W]   float32
// out = sum_k patches(x)*filters over 9x9 window + per-pixel bias.

#define KSZ 9
#define PADR 4
#define NB 4
#define HH 544
#define WW 960
#define PLANE (HH * WW)          // 522240

#define TILE_W 32                // 32 threads * 1 output (960/32 = 30 exact)
#define TILE_H 8

// 1 output/thread: warp-row quantum 10.4KB (half of R12) to cut the
// end-of-kernel ramp-down loss ~9% -> ~5%. Filter loads are scalar LDG.32,
// still perfectly coalesced (32 consecutive lanes -> one 128B line).
__global__ __launch_bounds__(256, 5)
void dfl_kernel(const float* __restrict__ x,
                const float* __restrict__ filt,
                const float* __restrict__ bias,
                float* __restrict__ out)
{
    const int n  = blockIdx.z;
    const int bw = blockIdx.x * TILE_W;
    const int bh = blockIdx.y * TILE_H;
    const int tx = threadIdx.x;           // 0..31
    const int ty = threadIdx.y;           // 0..7

    const int w = bw + tx;                // single output col
    const int h = bh + ty;                // output row (544 % 8 == 0)

    const float* __restrict__ xn = x + n * PLANE;
    const int pix = h * WW + w;

    // Per-thread column safety for the 9-wide window [w-4, w+4].
    const bool colsafe = (w >= PADR) && (w + PADR < WW);

    float acc = __ldcs(bias + n * PLANE + pix);

    const float* __restrict__ fbase = filt + (n * (KSZ * KSZ)) * PLANE + pix;

    #pragma unroll
    for (int dy = 0; dy < KSZ; ++dy) {
        // 9-wide x window for this row (L1/L2 hits), loaded before the
        // filter batch so xv drains into FMAs while f lands.
        float xv[KSZ];
        const int gr = h + dy - PADR;
        if ((unsigned)gr < (unsigned)HH) {
            const float* xr = xn + gr * WW + (w - PADR);
            if (colsafe) {
                #pragma unroll
                for (int j = 0; j < KSZ; ++j) xv[j] = __ldg(xr + j);
            } else {
                #pragma unroll
                for (int j = 0; j < KSZ; ++j) {
                    const int gc = w - PADR + j;
                    xv[j] = ((unsigned)gc < (unsigned)WW) ? __ldg(xr + j) : 0.0f;
                }
            }
        } else {
            #pragma unroll
            for (int j = 0; j < KSZ; ++j) xv[j] = 0.0f;   // no loads at all
        }

        // Full-row filter batch: 9 independent streaming LDG.32 (MLP 9),
        // evict-first so filters never displace x in L2.
        float f[KSZ];
        #pragma unroll
        for (int dx = 0; dx < KSZ; ++dx)
            f[dx] = __ldcs(fbase + (dy * KSZ + dx) * PLANE);

        #pragma unroll
        for (int dx = 0; dx < KSZ; ++dx)
            acc = fmaf(xv[dx], f[dx], acc);
    }

    __stcs(out + n * PLANE + pix, acc);
}

extern "C" void kernel_launch(void* const* d_in, const int* in_sizes, int n_in,
                              void* d_out, int out_size)
{
    const float* x    = (const float*)d_in[0];   // x_in
    const float* filt = (const float*)d_in[1];   // filters
    const float* bias = (const float*)d_in[2];   // filters_biases
    float* out        = (float*)d_out;

    dim3 block(32, 8, 1);
    dim3 grid(WW / TILE_W,   // 30 (exact)
              HH / TILE_H,   // 68
              NB);           // 4
    dfl_kernel<<<grid, block>>>(x, filt, bias, out);
}

// round 15
// speedup vs baseline: 1.0208x; 1.0208x over previous
#include <cuda_runtime.h>

// Problem constants (fixed by the dataset):
//   x_in:    [N,1,H,W]   float32
//   filters: [N,81,H,W]  float32
//   bias:    [N,1,H,W]   float32
//   out:     [N,1,H,W]   float32
// out = sum_k patches(x)*filters over 9x9 window + per-pixel bias.

#define KSZ 9
#define PADR 4
#define NB 4
#define HH 544
#define WW 960
#define PLANE (HH * WW)          // 522240

#define TILE_W 32                // 32 threads * 1 output (960/32 = 30 exact)
#define TILE_H 8

// 1 output/thread: warp-row quantum 10.4KB (half of R12) to cut the
// end-of-kernel ramp-down loss ~9% -> ~5%. Filter loads are scalar LDG.32,
// still perfectly coalesced (32 consecutive lanes -> one 128B line).
__global__ __launch_bounds__(256, 5)
void dfl_kernel(const float* __restrict__ x,
                const float* __restrict__ filt,
                const float* __restrict__ bias,
                float* __restrict__ out)
{
    const int n  = blockIdx.z;
    const int bw = blockIdx.x * TILE_W;
    const int bh = blockIdx.y * TILE_H;
    const int tx = threadIdx.x;           // 0..31
    const int ty = threadIdx.y;           // 0..7

    const int w = bw + tx;                // single output col
    const int h = bh + ty;                // output row (544 % 8 == 0)

    const float* __restrict__ xn = x + n * PLANE;
    const int pix = h * WW + w;

    // Per-thread column safety for the 9-wide window [w-4, w+4].
    const bool colsafe = (w >= PADR) && (w + PADR < WW);

    float acc = __ldcs(bias + n * PLANE + pix);

    const float* __restrict__ fbase = filt + (n * (KSZ * KSZ)) * PLANE + pix;

    #pragma unroll
    for (int dy = 0; dy < KSZ; ++dy) {
        // 9-wide x window for this row (L1/L2 hits), loaded before the
        // filter batch so xv drains into FMAs while f lands.
        float xv[KSZ];
        const int gr = h + dy - PADR;
        if ((unsigned)gr < (unsigned)HH) {
            const float* xr = xn + gr * WW + (w - PADR);
            if (colsafe) {
                #pragma unroll
                for (int j = 0; j < KSZ; ++j) xv[j] = __ldg(xr + j);
            } else {
                #pragma unroll
                for (int j = 0; j < KSZ; ++j) {
                    const int gc = w - PADR + j;
                    xv[j] = ((unsigned)gc < (unsigned)WW) ? __ldg(xr + j) : 0.0f;
                }
            }
        } else {
            #pragma unroll
            for (int j = 0; j < KSZ; ++j) xv[j] = 0.0f;   // no loads at all
        }

        // Full-row filter batch: 9 independent streaming LDG.32 (MLP 9),
        // evict-first so filters never displace x in L2.
        float f[KSZ];
        #pragma unroll
        for (int dx = 0; dx < KSZ; ++dx)
            f[dx] = __ldcs(fbase + (dy * KSZ + dx) * PLANE);

        #pragma unroll
        for (int dx = 0; dx < KSZ; ++dx)
            acc = fmaf(xv[dx], f[dx], acc);
    }

    __stcs(out + n * PLANE + pix, acc);
}

extern "C" void kernel_launch(void* const* d_in, const int* in_sizes, int n_in,
                              void* d_out, int out_size)
{
    const float* x    = (const float*)d_in[0];   // x_in
    const float* filt = (const float*)d_in[1];   // filters
    const float* bias = (const float*)d_in[2];   // filters_biases
    float* out        = (float*)d_out;

    dim3 block(32, 8, 1);
    dim3 grid(WW / TILE_W,   // 30 (exact)
              HH / TILE_H,   // 68
              NB);           // 4
    dfl_kernel<<<grid, block>>>(x, filt, bias, out);
}

// round 16
// speedup vs baseline: 1.0791x; 1.0571x over previous
#include <cuda_runtime.h>

// Problem constants (fixed by the dataset):
//   x_in:    [N,1,H,W]   float32
//   filters: [N,81,H,W]  float32
//   bias:    [N,1,H,W]   float32
//   out:     [N,1,H,W]   float32
// out = sum_k patches(x)*filters over 9x9 window + per-pixel bias.

#define KSZ 9
#define PADR 4
#define NB 4
#define HH 544
#define WW 960
#define PLANE (HH * WW)          // 522240

#define TILE_W 64                // 32 threads * 2 outputs (960/64 = 15 exact)
#define TILE_H 8

// R12 structure (float2 loads, exact grid, 3-tier x path) + explicit
// software pipeline on the filter stream: iteration dy prefetches dy+1's
// full 9x LDG.64 batch before draining dy's FMAs, so the warp always has
// 9-18 loads in flight and the DRAM request stream has no FMA-drain gaps.
// Peak live set ~58 regs -> 64-reg cap (4 CTAs/SM) without spilling.
__global__ __launch_bounds__(256, 4)
void dfl_kernel(const float* __restrict__ x,
                const float* __restrict__ filt,
                const float* __restrict__ bias,
                float* __restrict__ out)
{
    const int n  = blockIdx.z;
    const int bw = blockIdx.x * TILE_W;
    const int bh = blockIdx.y * TILE_H;
    const int tx = threadIdx.x;           // 0..31
    const int ty = threadIdx.y;           // 0..7

    const int w = bw + tx * 2;            // first of 2 output cols (even)
    const int h = bh + ty;                // output row (544 % 8 == 0)

    const float* __restrict__ xn = x + n * PLANE;
    const int pix = h * WW + w;

    // Per-thread column safety for the 10-wide window [w-4, w+6).
    const bool colsafe = (w >= PADR) && (w + 6 <= WW);

    const float2 b2 = __ldcs(reinterpret_cast<const float2*>(bias + n * PLANE + pix));
    float a0 = b2.x, a1 = b2.y;

    const float* __restrict__ fbase = filt + (n * (KSZ * KSZ)) * PLANE + pix;

    // ---- prologue: issue filter batch for dy = 0 ----
    float2 fa[KSZ];
    #pragma unroll
    for (int dx = 0; dx < KSZ; ++dx)
        fa[dx] = __ldcs(reinterpret_cast<const float2*>(fbase + dx * PLANE));

    #pragma unroll
    for (int dy = 0; dy < KSZ; ++dy) {
        // ---- prefetch next iteration's filter batch (dy+1) ----
        float2 fb[KSZ];
        if (dy + 1 < KSZ) {
            #pragma unroll
            for (int dx = 0; dx < KSZ; ++dx)
                fb[dx] = __ldcs(reinterpret_cast<const float2*>(
                                    fbase + ((dy + 1) * KSZ + dx) * PLANE));
        }

        // ---- x window for this row (L1/L2 hits) ----
        float xv[10];
        const int gr = h + dy - PADR;
        if ((unsigned)gr < (unsigned)HH) {
            if (colsafe) {
                const float* xr = xn + gr * WW + (w - PADR);
                const float2 p0 = *reinterpret_cast<const float2*>(xr + 0);
                const float2 p1 = *reinterpret_cast<const float2*>(xr + 2);
                const float2 p2 = *reinterpret_cast<const float2*>(xr + 4);
                const float2 p3 = *reinterpret_cast<const float2*>(xr + 6);
                const float2 p4 = *reinterpret_cast<const float2*>(xr + 8);
                xv[0] = p0.x; xv[1] = p0.y; xv[2] = p1.x; xv[3] = p1.y;
                xv[4] = p2.x; xv[5] = p2.y; xv[6] = p3.x; xv[7] = p3.y;
                xv[8] = p4.x; xv[9] = p4.y;
            } else {
                // Only threads with w in {0,2} or {956,958} ever land here.
                #pragma unroll
                for (int j = 0; j < 10; ++j) {
                    const int gc = w - PADR + j;
                    xv[j] = ((unsigned)gc < (unsigned)WW)
                                ? __ldg(xn + gr * WW + gc) : 0.0f;
                }
            }
        } else {
            #pragma unroll
            for (int j = 0; j < 10; ++j) xv[j] = 0.0f;   // no loads at all
        }

        // ---- drain current batch into the accumulators ----
        #pragma unroll
        for (int dx = 0; dx < KSZ; ++dx) {
            a0 = fmaf(xv[dx + 0], fa[dx].x, a0);
            a1 = fmaf(xv[dx + 1], fa[dx].y, a1);
        }

        // ---- rotate buffers (register rename; loop is fully unrolled) ----
        if (dy + 1 < KSZ) {
            #pragma unroll
            for (int dx = 0; dx < KSZ; ++dx)
                fa[dx] = fb[dx];
        }
    }

    __stcs(reinterpret_cast<float2*>(out + n * PLANE + pix), make_float2(a0, a1));
}

extern "C" void kernel_launch(void* const* d_in, const int* in_sizes, int n_in,
                              void* d_out, int out_size)
{
    const float* x    = (const float*)d_in[0];   // x_in
    const float* filt = (const float*)d_in[1];   // filters
    const float* bias = (const float*)d_in[2];   // filters_biases
    float* out        = (float*)d_out;

    dim3 block(32, 8, 1);
    dim3 grid(WW / TILE_W,   // 15 (exact)
              HH / TILE_H,   // 68
              NB);           // 4
    dfl_kernel<<<grid, block>>>(x, filt, bias, out);
}

// round 17
// speedup vs baseline: 1.0821x; 1.0028x over previous
#include <cuda_runtime.h>

// Problem constants (fixed by the dataset):
//   x_in:    [N,1,H,W]   float32
//   filters: [N,81,H,W]  float32
//   bias:    [N,1,H,W]   float32
//   out:     [N,1,H,W]   float32
// out = sum_k patches(x)*filters over 9x9 window + per-pixel bias.

#define KSZ 9
#define PADR 4
#define NB 4
#define HH 544
#define WW 960
#define PLANE (HH * WW)          // 522240

#define TILE_W 64                // 32 threads * 2 outputs (960/64 = 15 exact)
#define TILE_H 8

// R12 structure (best measured: 102.9us, DRAM 86.5%) with the occupancy cap
// raised to 6 CTAs/SM (42-reg cap; natural usage is 46, so only a 4-reg
// squeeze). 48 resident warps/SM vs 40 for ~20% more warp-level request
// parallelism across the FMA-drain gaps.
__global__ __launch_bounds__(256, 6)
void dfl_kernel(const float* __restrict__ x,
                const float* __restrict__ filt,
                const float* __restrict__ bias,
                float* __restrict__ out)
{
    const int n  = blockIdx.z;
    const int bw = blockIdx.x * TILE_W;
    const int bh = blockIdx.y * TILE_H;
    const int tx = threadIdx.x;           // 0..31
    const int ty = threadIdx.y;           // 0..7

    const int w = bw + tx * 2;            // first of 2 output cols (even)
    const int h = bh + ty;                // output row (544 % 8 == 0)

    const float* __restrict__ xn = x + n * PLANE;
    const int pix = h * WW + w;

    // Per-thread column safety for the 10-wide window [w-4, w+6).
    const bool colsafe = (w >= PADR) && (w + 6 <= WW);

    const float2 b2 = __ldcs(reinterpret_cast<const float2*>(bias + n * PLANE + pix));
    float a0 = b2.x, a1 = b2.y;

    const float* __restrict__ fbase = filt + (n * (KSZ * KSZ)) * PLANE + pix;

    #pragma unroll
    for (int dy = 0; dy < KSZ; ++dy) {
        // 10-wide x window for this row: cols [w-4 .. w+5], all 8B-aligned.
        // L1/L2 hits; loaded first so xv drains into FMAs while f lands.
        float xv[10];
        const int gr = h + dy - PADR;
        if ((unsigned)gr < (unsigned)HH) {
            if (colsafe) {
                const float* xr = xn + gr * WW + (w - PADR);
                const float2 p0 = *reinterpret_cast<const float2*>(xr + 0);
                const float2 p1 = *reinterpret_cast<const float2*>(xr + 2);
                const float2 p2 = *reinterpret_cast<const float2*>(xr + 4);
                const float2 p3 = *reinterpret_cast<const float2*>(xr + 6);
                const float2 p4 = *reinterpret_cast<const float2*>(xr + 8);
                xv[0] = p0.x; xv[1] = p0.y; xv[2] = p1.x; xv[3] = p1.y;
                xv[4] = p2.x; xv[5] = p2.y; xv[6] = p3.x; xv[7] = p3.y;
                xv[8] = p4.x; xv[9] = p4.y;
            } else {
                // Only threads with w in {0,2} or {956,958} ever land here.
                #pragma unroll
                for (int j = 0; j < 10; ++j) {
                    const int gc = w - PADR + j;
                    xv[j] = ((unsigned)gc < (unsigned)WW)
                                ? __ldg(xn + gr * WW + gc) : 0.0f;
                }
            }
        } else {
            #pragma unroll
            for (int j = 0; j < 10; ++j) xv[j] = 0.0f;   // no loads at all
        }

        // Full-row filter batch: 9 independent streaming LDG.64 (MLP 9),
        // evict-first so filters never displace x in L2.
        float2 f[KSZ];
        #pragma unroll
        for (int dx = 0; dx < KSZ; ++dx)
            f[dx] = __ldcs(reinterpret_cast<const float2*>(fbase + (dy * KSZ + dx) * PLANE));

        #pragma unroll
        for (int dx = 0; dx < KSZ; ++dx) {
            a0 = fmaf(xv[dx + 0], f[dx].x, a0);
            a1 = fmaf(xv[dx + 1], f[dx].y, a1);
        }
    }

    __stcs(reinterpret_cast<float2*>(out + n * PLANE + pix), make_float2(a0, a1));
}

extern "C" void kernel_launch(void* const* d_in, const int* in_sizes, int n_in,
                              void* d_out, int out_size)
{
    const float* x    = (const float*)d_in[0];   // x_in
    const float* filt = (const float*)d_in[1];   // filters
    const float* bias = (const float*)d_in[2];   // filters_biases
    float* out        = (float*)d_out;

    dim3 block(32, 8, 1);
    dim3 grid(WW / TILE_W,   // 15 (exact)
              HH / TILE_H,   // 68
              NB);           // 4
    dfl_kernel<<<grid, block>>>(x, filt, bias, out);
}